// round 1
// baseline (speedup 1.0000x reference)
#include <cuda_runtime.h>
#include <cstdint>

#define HIDDEN 4096
#define INTER  14336
#define PREDH  1024
#define SEQ    4096
#define HC     716
#define NBINS  4096

// ---------------- device scratch (static allocation only) ----------------
__device__ __align__(256) float    g_p[PREDH];
__device__ __align__(256) unsigned g_key[INTER];
__device__ int g_hist[NBINS];
__device__ int g_cnt[4];        // [0]=direct count, [1]=candidate count
__device__ int g_sel[2];        // [0]=threshold bin, [1]=count strictly above bin
__device__ __align__(256) int g_idx[HC];
__device__ int      g_cand_idx[INTER];
__device__ unsigned g_cand_key[INTER];
__device__ __align__(256) float g_gate[(size_t)SEQ * HC];
__device__ __align__(256) float g_t[(size_t)SEQ * HC];
__device__ __align__(256) float g_wd[(size_t)HIDDEN * HC];

// ---------------- small kernels ----------------
__global__ void k_init() {
    int t = blockIdx.x * blockDim.x + threadIdx.x;
    if (t < NBINS) g_hist[t] = 0;
    if (t < 4) g_cnt[t] = 0;
}

// p = W1 @ x_last   (1024 x 4096 GEMV, fp64 accumulate: predictor must be exact)
__global__ void k_pred1(const float* __restrict__ x, const float* __restrict__ W1) {
    const float* xl = x + (size_t)(SEQ - 1) * HIDDEN;
    int warp = (blockIdx.x * blockDim.x + threadIdx.x) >> 5;
    int lane = threadIdx.x & 31;
    if (warp >= PREDH) return;
    const float* w = W1 + (size_t)warp * HIDDEN;
    double s = 0.0;
    for (int k = lane; k < HIDDEN; k += 32)
        s += (double)w[k] * (double)xl[k];
    for (int o = 16; o; o >>= 1) s += __shfl_down_sync(0xffffffffu, s, o);
    if (lane == 0) g_p[warp] = (float)s;
}

// h = W2 @ p ; flip to sortable key; 12-bit histogram
__global__ void k_pred2(const float* __restrict__ W2) {
    int warp = (blockIdx.x * blockDim.x + threadIdx.x) >> 5;
    int lane = threadIdx.x & 31;
    if (warp >= INTER) return;
    const float* w = W2 + (size_t)warp * PREDH;
    double s = 0.0;
    for (int k = lane; k < PREDH; k += 32)
        s += (double)w[k] * (double)g_p[k];
    for (int o = 16; o; o >>= 1) s += __shfl_down_sync(0xffffffffu, s, o);
    if (lane == 0) {
        float v = (float)s;
        unsigned u = __float_as_uint(v);
        u = (u & 0x80000000u) ? ~u : (u | 0x80000000u);  // larger float -> larger key
        g_key[warp] = u;
        atomicAdd(&g_hist[u >> 20], 1);
    }
}

// find the histogram bin containing the 716th largest key
__global__ void k_thresh() {
    __shared__ int sh[NBINS];
    for (int i = threadIdx.x; i < NBINS; i += blockDim.x) sh[i] = g_hist[i];
    __syncthreads();
    if (threadIdx.x == 0) {
        int acc = 0;
        for (int b = NBINS - 1; b >= 0; --b) {
            int c = sh[b];
            if (acc + c >= HC) { g_sel[0] = b; g_sel[1] = acc; break; }
            acc += c;
        }
    }
}

// strictly-above-bin -> direct select ; in-bin -> candidate buffer
__global__ void k_collect() {
    int i = blockIdx.x * blockDim.x + threadIdx.x;
    if (i >= INTER) return;
    unsigned key = g_key[i];
    int bin = g_sel[0];
    int b = (int)(key >> 20);
    if (b > bin) {
        int p = atomicAdd(&g_cnt[0], 1);
        g_idx[p] = i;
    } else if (b == bin) {
        int p = atomicAdd(&g_cnt[1], 1);
        g_cand_idx[p] = i;
        g_cand_key[p] = key;
    }
}

// exact rank of boundary-bin candidates (tie-break: lower index wins, matches lax.top_k)
__global__ void k_rank() {
    __shared__ unsigned sk[4096];
    __shared__ int      si[4096];
    int m = g_cnt[1];
    int above = g_sel[1];
    int need = HC - above;
    bool use_s = (m <= 4096);
    if (use_s) {
        for (int i = threadIdx.x; i < m; i += blockDim.x) {
            sk[i] = g_cand_key[i];
            si[i] = g_cand_idx[i];
        }
    }
    __syncthreads();
    for (int j = threadIdx.x; j < m; j += blockDim.x) {
        unsigned kj = use_s ? sk[j] : g_cand_key[j];
        int ij      = use_s ? si[j] : g_cand_idx[j];
        int r = 0;
        for (int l = 0; l < m; ++l) {
            unsigned kl = use_s ? sk[l] : g_cand_key[l];
            int il      = use_s ? si[l] : g_cand_idx[l];
            r += (int)((kl > kj) || (kl == kj && il < ij));
        }
        if (r < need) g_idx[above + r] = ij;
    }
}

// pack Wd[:, idx] -> g_wd[h][k]  (warp per output row; coalesced writes)
__global__ void k_gather(const float* __restrict__ Wd) {
    int warp = (blockIdx.x * blockDim.x + threadIdx.x) >> 5;
    int lane = threadIdx.x & 31;
    if (warp >= HIDDEN) return;
    const float* row = Wd + (size_t)warp * INTER;
    float* dst = g_wd + (size_t)warp * HC;
    for (int k = lane; k < HC; k += 32)
        dst[k] = __ldg(row + __ldg(&g_idx[k]));
}

// ---------------- tf32 mma GEMM:  C[M,N] = A[M,K] @ rows(B)[N,K]^T ----------------
#define BM 128
#define BN 128
#define BK 16
#define KST 20  // smem row stride in floats: conflict-free for the mma frag pattern

__device__ __forceinline__ unsigned f2tf(float f) {
    unsigned r;
    asm("cvt.rna.tf32.f32 %0, %1;" : "=r"(r) : "f"(f));
    return r;
}
__device__ __forceinline__ unsigned smem_u32(const void* p) {
    return (unsigned)__cvta_generic_to_shared(p);
}
__device__ __forceinline__ void cpasync16(unsigned dst, const void* src, bool pred) {
    int sz = pred ? 16 : 0;
    asm volatile("cp.async.cg.shared.global [%0], [%1], 16, %2;\n"
                 :: "r"(dst), "l"(src), "r"(sz));
}

// epi: 0 = plain store, 1 = C = silu(gatebuf) * acc, 2 = plain store
__global__ void __launch_bounds__(256, 2) k_gemm(
    const float* __restrict__ A, const float* __restrict__ B,
    float* __restrict__ C, const float* __restrict__ gatebuf,
    int M, int N, int K, int lda, int ldb, int ldc,
    int gather, int epi)
{
    __shared__ float As[2][BM * KST];
    __shared__ float Bs[2][BN * KST];

    int tid = threadIdx.x;
    int lane = tid & 31;
    int warp = tid >> 5;
    int wm = warp >> 2;  // 0..1  (64-row slabs)
    int wn = warp & 3;   // 0..3  (32-col slabs)
    int bm = blockIdx.y * BM;
    int bn = blockIdx.x * BN;

    // tile-load mapping: 256 threads, each does 2 A + 2 B 16B cp.asyncs
    int lk4 = tid >> 6;   // 0..3 -> k offset lk4*4
    int lrow = tid & 63;  // rows lrow and lrow+64

    const float* a_src0 = A + (size_t)(bm + lrow) * lda + lk4 * 4;
    const float* a_src1 = A + (size_t)(bm + lrow + 64) * lda + lk4 * 4;

    int n0 = bn + lrow, n1 = bn + lrow + 64;
    bool bv0 = n0 < N, bv1 = n1 < N;
    long rb0, rb1;
    if (gather) {
        rb0 = bv0 ? (long)__ldg(&g_idx[n0]) : 0;
        rb1 = bv1 ? (long)__ldg(&g_idx[n1]) : 0;
    } else {
        rb0 = bv0 ? n0 : 0;
        rb1 = bv1 ? n1 : 0;
    }
    const float* b_src0 = B + (size_t)rb0 * ldb + lk4 * 4;
    const float* b_src1 = B + (size_t)rb1 * ldb + lk4 * 4;

    unsigned a_dst0[2], a_dst1[2], b_dst0[2], b_dst1[2];
#pragma unroll
    for (int b = 0; b < 2; b++) {
        a_dst0[b] = smem_u32(&As[b][lrow * KST + lk4 * 4]);
        a_dst1[b] = smem_u32(&As[b][(lrow + 64) * KST + lk4 * 4]);
        b_dst0[b] = smem_u32(&Bs[b][lrow * KST + lk4 * 4]);
        b_dst1[b] = smem_u32(&Bs[b][(lrow + 64) * KST + lk4 * 4]);
    }

    float acc[4][4][4];
#pragma unroll
    for (int i = 0; i < 4; i++)
#pragma unroll
        for (int j = 0; j < 4; j++)
#pragma unroll
            for (int q = 0; q < 4; q++) acc[i][j][q] = 0.f;

    int NT = (K + BK - 1) / BK;

    auto load_tile = [&](int kt, int buf) {
        int k0 = kt * BK;
        bool kv = (k0 + lk4 * 4) < K;  // K divisible by 4, so vector-granule guard is exact
        cpasync16(a_dst0[buf], a_src0 + k0, kv);
        cpasync16(a_dst1[buf], a_src1 + k0, kv);
        cpasync16(b_dst0[buf], b_src0 + k0, kv && bv0);
        cpasync16(b_dst1[buf], b_src1 + k0, kv && bv1);
        asm volatile("cp.async.commit_group;\n");
    };

    load_tile(0, 0);

    for (int kt = 0; kt < NT; ++kt) {
        int buf = kt & 1;
        if (kt + 1 < NT) {
            load_tile(kt + 1, buf ^ 1);
            asm volatile("cp.async.wait_group 1;\n");
        } else {
            asm volatile("cp.async.wait_group 0;\n");
        }
        __syncthreads();

        const float* as = As[buf];
        const float* bs = Bs[buf];
#pragma unroll
        for (int ks = 0; ks < 2; ++ks) {
            unsigned af[4][4], bf[4][2];
            int c = ks * 8 + (lane & 3);
#pragma unroll
            for (int mi = 0; mi < 4; ++mi) {
                int r = wm * 64 + mi * 16 + (lane >> 2);
                af[mi][0] = f2tf(as[r * KST + c]);
                af[mi][1] = f2tf(as[(r + 8) * KST + c]);
                af[mi][2] = f2tf(as[r * KST + c + 4]);
                af[mi][3] = f2tf(as[(r + 8) * KST + c + 4]);
            }
#pragma unroll
            for (int ni = 0; ni < 4; ++ni) {
                int n = wn * 32 + ni * 8 + (lane >> 2);
                bf[ni][0] = f2tf(bs[n * KST + c]);
                bf[ni][1] = f2tf(bs[n * KST + c + 4]);
            }
#pragma unroll
            for (int mi = 0; mi < 4; ++mi)
#pragma unroll
                for (int ni = 0; ni < 4; ++ni) {
                    asm volatile(
                        "mma.sync.aligned.m16n8k8.row.col.f32.tf32.tf32.f32 "
                        "{%0,%1,%2,%3}, {%4,%5,%6,%7}, {%8,%9}, {%0,%1,%2,%3};\n"
                        : "+f"(acc[mi][ni][0]), "+f"(acc[mi][ni][1]),
                          "+f"(acc[mi][ni][2]), "+f"(acc[mi][ni][3])
                        : "r"(af[mi][0]), "r"(af[mi][1]), "r"(af[mi][2]), "r"(af[mi][3]),
                          "r"(bf[ni][0]), "r"(bf[ni][1]));
                }
        }
        __syncthreads();
    }

    // epilogue
#pragma unroll
    for (int mi = 0; mi < 4; ++mi) {
        int r0 = bm + wm * 64 + mi * 16 + (lane >> 2);
        int r1 = r0 + 8;
#pragma unroll
        for (int ni = 0; ni < 4; ++ni) {
            int cc = bn + wn * 32 + ni * 8 + (lane & 3) * 2;
            if (cc < N) {  // N is even; pair is all-or-nothing
                float v0 = acc[mi][ni][0], v1 = acc[mi][ni][1];
                float v2 = acc[mi][ni][2], v3 = acc[mi][ni][3];
                if (epi == 1) {
                    const float* gp0 = gatebuf + (size_t)r0 * ldc + cc;
                    const float* gp1 = gatebuf + (size_t)r1 * ldc + cc;
                    float g0 = __ldg(gp0), g1 = __ldg(gp0 + 1);
                    float g2 = __ldg(gp1), g3 = __ldg(gp1 + 1);
                    v0 *= g0 / (1.f + __expf(-g0));
                    v1 *= g1 / (1.f + __expf(-g1));
                    v2 *= g2 / (1.f + __expf(-g2));
                    v3 *= g3 / (1.f + __expf(-g3));
                }
                *(float2*)(C + (size_t)r0 * ldc + cc) = make_float2(v0, v1);
                *(float2*)(C + (size_t)r1 * ldc + cc) = make_float2(v2, v3);
            }
        }
    }
}

// ---------------- launch ----------------
extern "C" void kernel_launch(void* const* d_in, const int* in_sizes, int n_in,
                              void* d_out, int out_size) {
    (void)in_sizes; (void)n_in; (void)out_size;
    const float* x  = (const float*)d_in[0];
    const float* Wg = (const float*)d_in[1];
    const float* Wu = (const float*)d_in[2];
    const float* Wd = (const float*)d_in[3];
    const float* W1 = (const float*)d_in[4];
    const float* W2 = (const float*)d_in[5];
    float* out = (float*)d_out;

    float *pg = nullptr, *pt = nullptr, *pw = nullptr;
    cudaGetSymbolAddress((void**)&pg, g_gate);
    cudaGetSymbolAddress((void**)&pt, g_t);
    cudaGetSymbolAddress((void**)&pw, g_wd);

    k_init<<<16, 256>>>();
    k_pred1<<<(PREDH * 32) / 256, 256>>>(x, W1);
    k_pred2<<<(INTER * 32) / 256, 256>>>(W2);
    k_thresh<<<1, 1024>>>();
    k_collect<<<(INTER + 255) / 256, 256>>>();
    k_rank<<<1, 512>>>();
    k_gather<<<(HIDDEN * 32) / 256, 256>>>(Wd);

    dim3 g12((HC + BN - 1) / BN, SEQ / BM);
    // gate = x @ Wg[idx]^T
    k_gemm<<<g12, 256>>>(x, Wg, pg, nullptr,
                         SEQ, HC, HIDDEN, HIDDEN, HIDDEN, HC, 1, 0);
    // t = silu(gate) * (x @ Wu[idx]^T)
    k_gemm<<<g12, 256>>>(x, Wu, pt, pg,
                         SEQ, HC, HIDDEN, HIDDEN, HIDDEN, HC, 1, 1);
    // out = t @ Wd_packed^T
    dim3 g3(HIDDEN / BN, SEQ / BM);
    k_gemm<<<g3, 256>>>(pt, pw, out, nullptr,
                        SEQ, HIDDEN, HC, HC, HC, HIDDEN, 0, 2);
}

// round 2
// speedup vs baseline: 1.0004x; 1.0004x over previous
#include <cuda_runtime.h>
#include <cstdint>

#define HIDDEN 4096
#define INTER  14336
#define PREDH  1024
#define SEQ    4096
#define HC     716
#define NBINS  4096

// ---------------- device scratch (static allocation only) ----------------
__device__ __align__(256) float    g_p[PREDH];
__device__ __align__(256) unsigned g_key[INTER];
__device__ int g_hist[NBINS];
__device__ int g_cnt[4];        // [0]=direct count, [1]=candidate count
__device__ int g_sel[2];        // [0]=threshold bin, [1]=count strictly above bin
__device__ __align__(256) int g_idx[HC];
__device__ int      g_cand_idx[INTER];
__device__ unsigned g_cand_key[INTER];
__device__ __align__(256) float g_gate[(size_t)SEQ * HC];
__device__ __align__(256) float g_t[(size_t)SEQ * HC];
__device__ __align__(256) float g_wd[(size_t)HIDDEN * HC];

// ---------------- small kernels ----------------
__global__ void k_init() {
    int t = blockIdx.x * blockDim.x + threadIdx.x;
    if (t < NBINS) g_hist[t] = 0;
    if (t < 4) g_cnt[t] = 0;
}

// p = W1 @ x_last   (1024 x 4096 GEMV, fp64 accumulate: predictor must be exact)
__global__ void k_pred1(const float* __restrict__ x, const float* __restrict__ W1) {
    const float* xl = x + (size_t)(SEQ - 1) * HIDDEN;
    int warp = (blockIdx.x * blockDim.x + threadIdx.x) >> 5;
    int lane = threadIdx.x & 31;
    if (warp >= PREDH) return;
    const float* w = W1 + (size_t)warp * HIDDEN;
    double s = 0.0;
    for (int k = lane; k < HIDDEN; k += 32)
        s += (double)w[k] * (double)xl[k];
    for (int o = 16; o; o >>= 1) s += __shfl_down_sync(0xffffffffu, s, o);
    if (lane == 0) g_p[warp] = (float)s;
}

// h = W2 @ p ; flip to sortable key; 12-bit histogram
__global__ void k_pred2(const float* __restrict__ W2) {
    int warp = (blockIdx.x * blockDim.x + threadIdx.x) >> 5;
    int lane = threadIdx.x & 31;
    if (warp >= INTER) return;
    const float* w = W2 + (size_t)warp * PREDH;
    double s = 0.0;
    for (int k = lane; k < PREDH; k += 32)
        s += (double)w[k] * (double)g_p[k];
    for (int o = 16; o; o >>= 1) s += __shfl_down_sync(0xffffffffu, s, o);
    if (lane == 0) {
        float v = (float)s;
        unsigned u = __float_as_uint(v);
        u = (u & 0x80000000u) ? ~u : (u | 0x80000000u);  // larger float -> larger key
        g_key[warp] = u;
        atomicAdd(&g_hist[u >> 20], 1);
    }
}

// find the histogram bin containing the 716th largest key
__global__ void k_thresh() {
    __shared__ int sh[NBINS];
    for (int i = threadIdx.x; i < NBINS; i += blockDim.x) sh[i] = g_hist[i];
    __syncthreads();
    if (threadIdx.x == 0) {
        int acc = 0;
        for (int b = NBINS - 1; b >= 0; --b) {
            int c = sh[b];
            if (acc + c >= HC) { g_sel[0] = b; g_sel[1] = acc; break; }
            acc += c;
        }
    }
}

// strictly-above-bin -> direct select ; in-bin -> candidate buffer
__global__ void k_collect() {
    int i = blockIdx.x * blockDim.x + threadIdx.x;
    if (i >= INTER) return;
    unsigned key = g_key[i];
    int bin = g_sel[0];
    int b = (int)(key >> 20);
    if (b > bin) {
        int p = atomicAdd(&g_cnt[0], 1);
        g_idx[p] = i;
    } else if (b == bin) {
        int p = atomicAdd(&g_cnt[1], 1);
        g_cand_idx[p] = i;
        g_cand_key[p] = key;
    }
}

// exact rank of boundary-bin candidates (tie-break: lower index wins, matches lax.top_k)
__global__ void k_rank() {
    __shared__ unsigned sk[4096];
    __shared__ int      si[4096];
    int m = g_cnt[1];
    int above = g_sel[1];
    int need = HC - above;
    bool use_s = (m <= 4096);
    if (use_s) {
        for (int i = threadIdx.x; i < m; i += blockDim.x) {
            sk[i] = g_cand_key[i];
            si[i] = g_cand_idx[i];
        }
    }
    __syncthreads();
    for (int j = threadIdx.x; j < m; j += blockDim.x) {
        unsigned kj = use_s ? sk[j] : g_cand_key[j];
        int ij      = use_s ? si[j] : g_cand_idx[j];
        int r = 0;
        for (int l = 0; l < m; ++l) {
            unsigned kl = use_s ? sk[l] : g_cand_key[l];
            int il      = use_s ? si[l] : g_cand_idx[l];
            r += (int)((kl > kj) || (kl == kj && il < ij));
        }
        if (r < need) g_idx[above + r] = ij;
    }
}

// pack Wd[:, idx] -> g_wd[h][k]  (warp per output row; coalesced writes)
__global__ void k_gather(const float* __restrict__ Wd) {
    int warp = (blockIdx.x * blockDim.x + threadIdx.x) >> 5;
    int lane = threadIdx.x & 31;
    if (warp >= HIDDEN) return;
    const float* row = Wd + (size_t)warp * INTER;
    float* dst = g_wd + (size_t)warp * HC;
    for (int k = lane; k < HC; k += 32)
        dst[k] = __ldg(row + __ldg(&g_idx[k]));
}

// ---------------- tf32 mma GEMM:  C[M,N] = A[M,K] @ rows(B)[N,K]^T ----------------
#define BM 128
#define BN 128
#define BK 16
#define KST 20  // smem row stride in floats: conflict-free for the mma frag pattern

__device__ __forceinline__ unsigned f2tf(float f) {
    unsigned r;
    asm("cvt.rna.tf32.f32 %0, %1;" : "=r"(r) : "f"(f));
    return r;
}
__device__ __forceinline__ unsigned smem_u32(const void* p) {
    return (unsigned)__cvta_generic_to_shared(p);
}
__device__ __forceinline__ void cpasync16(unsigned dst, const void* src, bool pred) {
    int sz = pred ? 16 : 0;
    asm volatile("cp.async.cg.shared.global [%0], [%1], 16, %2;\n"
                 :: "r"(dst), "l"(src), "r"(sz));
}

// epi: 0 = plain store, 1 = C = silu(gatebuf) * acc, 2 = plain store
__global__ void __launch_bounds__(256, 2) k_gemm(
    const float* __restrict__ A, const float* __restrict__ B,
    float* __restrict__ C, const float* __restrict__ gatebuf,
    int M, int N, int K, int lda, int ldb, int ldc,
    int gather, int epi)
{
    __shared__ float As[2][BM * KST];
    __shared__ float Bs[2][BN * KST];

    int tid = threadIdx.x;
    int lane = tid & 31;
    int warp = tid >> 5;
    int wm = warp >> 2;  // 0..1  (64-row slabs)
    int wn = warp & 3;   // 0..3  (32-col slabs)
    int bm = blockIdx.y * BM;
    int bn = blockIdx.x * BN;

    // tile-load mapping: 256 threads, each does 2 A + 2 B 16B cp.asyncs
    int lk4 = tid >> 6;   // 0..3 -> k offset lk4*4
    int lrow = tid & 63;  // rows lrow and lrow+64

    const float* a_src0 = A + (size_t)(bm + lrow) * lda + lk4 * 4;
    const float* a_src1 = A + (size_t)(bm + lrow + 64) * lda + lk4 * 4;

    int n0 = bn + lrow, n1 = bn + lrow + 64;
    bool bv0 = n0 < N, bv1 = n1 < N;
    long rb0, rb1;
    if (gather) {
        rb0 = bv0 ? (long)__ldg(&g_idx[n0]) : 0;
        rb1 = bv1 ? (long)__ldg(&g_idx[n1]) : 0;
    } else {
        rb0 = bv0 ? n0 : 0;
        rb1 = bv1 ? n1 : 0;
    }
    const float* b_src0 = B + (size_t)rb0 * ldb + lk4 * 4;
    const float* b_src1 = B + (size_t)rb1 * ldb + lk4 * 4;

    unsigned a_dst0[2], a_dst1[2], b_dst0[2], b_dst1[2];
#pragma unroll
    for (int b = 0; b < 2; b++) {
        a_dst0[b] = smem_u32(&As[b][lrow * KST + lk4 * 4]);
        a_dst1[b] = smem_u32(&As[b][(lrow + 64) * KST + lk4 * 4]);
        b_dst0[b] = smem_u32(&Bs[b][lrow * KST + lk4 * 4]);
        b_dst1[b] = smem_u32(&Bs[b][(lrow + 64) * KST + lk4 * 4]);
    }

    float acc[4][4][4];
#pragma unroll
    for (int i = 0; i < 4; i++)
#pragma unroll
        for (int j = 0; j < 4; j++)
#pragma unroll
            for (int q = 0; q < 4; q++) acc[i][j][q] = 0.f;

    int NT = (K + BK - 1) / BK;

    auto load_tile = [&](int kt, int buf) {
        int k0 = kt * BK;
        bool kv = (k0 + lk4 * 4) < K;  // K divisible by 4, so vector-granule guard is exact
        cpasync16(a_dst0[buf], a_src0 + k0, kv);
        cpasync16(a_dst1[buf], a_src1 + k0, kv);
        cpasync16(b_dst0[buf], b_src0 + k0, kv && bv0);
        cpasync16(b_dst1[buf], b_src1 + k0, kv && bv1);
        asm volatile("cp.async.commit_group;\n");
    };

    load_tile(0, 0);

    for (int kt = 0; kt < NT; ++kt) {
        int buf = kt & 1;
        if (kt + 1 < NT) {
            load_tile(kt + 1, buf ^ 1);
            asm volatile("cp.async.wait_group 1;\n");
        } else {
            asm volatile("cp.async.wait_group 0;\n");
        }
        __syncthreads();

        const float* as = As[buf];
        const float* bs = Bs[buf];
#pragma unroll
        for (int ks = 0; ks < 2; ++ks) {
            unsigned af[4][4], bf[4][2];
            int c = ks * 8 + (lane & 3);
#pragma unroll
            for (int mi = 0; mi < 4; ++mi) {
                int r = wm * 64 + mi * 16 + (lane >> 2);
                af[mi][0] = f2tf(as[r * KST + c]);
                af[mi][1] = f2tf(as[(r + 8) * KST + c]);
                af[mi][2] = f2tf(as[r * KST + c + 4]);
                af[mi][3] = f2tf(as[(r + 8) * KST + c + 4]);
            }
#pragma unroll
            for (int ni = 0; ni < 4; ++ni) {
                int n = wn * 32 + ni * 8 + (lane >> 2);
                bf[ni][0] = f2tf(bs[n * KST + c]);
                bf[ni][1] = f2tf(bs[n * KST + c + 4]);
            }
#pragma unroll
            for (int mi = 0; mi < 4; ++mi)
#pragma unroll
                for (int ni = 0; ni < 4; ++ni) {
                    asm volatile(
                        "mma.sync.aligned.m16n8k8.row.col.f32.tf32.tf32.f32 "
                        "{%0,%1,%2,%3}, {%4,%5,%6,%7}, {%8,%9}, {%0,%1,%2,%3};\n"
                        : "+f"(acc[mi][ni][0]), "+f"(acc[mi][ni][1]),
                          "+f"(acc[mi][ni][2]), "+f"(acc[mi][ni][3])
                        : "r"(af[mi][0]), "r"(af[mi][1]), "r"(af[mi][2]), "r"(af[mi][3]),
                          "r"(bf[ni][0]), "r"(bf[ni][1]));
                }
        }
        __syncthreads();
    }

    // epilogue
#pragma unroll
    for (int mi = 0; mi < 4; ++mi) {
        int r0 = bm + wm * 64 + mi * 16 + (lane >> 2);
        int r1 = r0 + 8;
#pragma unroll
        for (int ni = 0; ni < 4; ++ni) {
            int cc = bn + wn * 32 + ni * 8 + (lane & 3) * 2;
            if (cc < N) {  // N is even; pair is all-or-nothing
                float v0 = acc[mi][ni][0], v1 = acc[mi][ni][1];
                float v2 = acc[mi][ni][2], v3 = acc[mi][ni][3];
                if (epi == 1) {
                    const float* gp0 = gatebuf + (size_t)r0 * ldc + cc;
                    const float* gp1 = gatebuf + (size_t)r1 * ldc + cc;
                    float g0 = __ldg(gp0), g1 = __ldg(gp0 + 1);
                    float g2 = __ldg(gp1), g3 = __ldg(gp1 + 1);
                    v0 *= g0 / (1.f + __expf(-g0));
                    v1 *= g1 / (1.f + __expf(-g1));
                    v2 *= g2 / (1.f + __expf(-g2));
                    v3 *= g3 / (1.f + __expf(-g3));
                }
                *(float2*)(C + (size_t)r0 * ldc + cc) = make_float2(v0, v1);
                *(float2*)(C + (size_t)r1 * ldc + cc) = make_float2(v2, v3);
            }
        }
    }
}

// ---------------- launch ----------------
extern "C" void kernel_launch(void* const* d_in, const int* in_sizes, int n_in,
                              void* d_out, int out_size) {
    (void)in_sizes; (void)n_in; (void)out_size;
    const float* x  = (const float*)d_in[0];
    const float* Wg = (const float*)d_in[1];
    const float* Wu = (const float*)d_in[2];
    const float* Wd = (const float*)d_in[3];
    const float* W1 = (const float*)d_in[4];
    const float* W2 = (const float*)d_in[5];
    float* out = (float*)d_out;

    float *pg = nullptr, *pt = nullptr, *pw = nullptr;
    cudaGetSymbolAddress((void**)&pg, g_gate);
    cudaGetSymbolAddress((void**)&pt, g_t);
    cudaGetSymbolAddress((void**)&pw, g_wd);

    k_init<<<16, 256>>>();
    k_pred1<<<(PREDH * 32) / 256, 256>>>(x, W1);
    k_pred2<<<(INTER * 32) / 256, 256>>>(W2);
    k_thresh<<<1, 1024>>>();
    k_collect<<<(INTER + 255) / 256, 256>>>();
    k_rank<<<1, 512>>>();
    k_gather<<<(HIDDEN * 32) / 256, 256>>>(Wd);

    dim3 g12((HC + BN - 1) / BN, SEQ / BM);
    // gate = x @ Wg[idx]^T
    k_gemm<<<g12, 256>>>(x, Wg, pg, nullptr,
                         SEQ, HC, HIDDEN, HIDDEN, HIDDEN, HC, 1, 0);
    // t = silu(gate) * (x @ Wu[idx]^T)
    k_gemm<<<g12, 256>>>(x, Wu, pt, pg,
                         SEQ, HC, HIDDEN, HIDDEN, HIDDEN, HC, 1, 1);
    // out = t @ Wd_packed^T
    dim3 g3(HIDDEN / BN, SEQ / BM);
    k_gemm<<<g3, 256>>>(pt, pw, out, nullptr,
                        SEQ, HIDDEN, HC, HC, HC, HIDDEN, 0, 2);
}

// round 4
// speedup vs baseline: 1.5010x; 1.5004x over previous
#include <cuda_runtime.h>
#include <cstdint>

#define HIDDEN 4096
#define INTER  14336
#define PREDH  1024
#define SEQ    4096
#define HC     716
#define NPAD   1536   // interleaved gate/up rows, padded
#define KPAD   768    // t / Wd K dim, padded
#define NBINS  4096

// ---------------- device scratch ----------------
__device__ __align__(256) float    g_p[PREDH];
__device__ __align__(256) unsigned g_key[INTER];
__device__ int g_hist[NBINS];
__device__ int g_cnt[4];
__device__ int g_sel[2];
__device__ __align__(256) int g_idx[HC];
__device__ int      g_cand_idx[INTER];
__device__ unsigned g_cand_key[INTER];
__device__ __align__(1024) float g_xr[(size_t)SEQ * HIDDEN];   // x, tf32-rounded, k-permuted
__device__ __align__(1024) float g_b1[(size_t)NPAD * HIDDEN];  // interleaved Wg/Wu, rounded, permuted
__device__ __align__(1024) float g_wd[(size_t)HIDDEN * KPAD];  // gathered Wd, rounded, permuted
__device__ __align__(1024) float g_t [(size_t)SEQ * KPAD];     // silu(g)*u, rounded, permuted

// ---------------- helpers ----------------
__device__ __forceinline__ float tfr(float f) {
    unsigned r; asm("cvt.rna.tf32.f32 %0, %1;" : "=r"(r) : "f"(f));
    return __uint_as_float(r);
}
__device__ __forceinline__ unsigned smem_u32(const void* p) {
    return (unsigned)__cvta_generic_to_shared(p);
}
__device__ __forceinline__ void cp16(unsigned dst, const void* src) {
    asm volatile("cp.async.cg.shared.global [%0], [%1], 16;" :: "r"(dst), "l"(src) : "memory");
}
__device__ __forceinline__ void mma8(float* d, unsigned a0, unsigned a1, unsigned a2,
                                     unsigned a3, unsigned b0, unsigned b1) {
    asm volatile(
        "mma.sync.aligned.m16n8k8.row.col.f32.tf32.tf32.f32 "
        "{%0,%1,%2,%3}, {%4,%5,%6,%7}, {%8,%9}, {%0,%1,%2,%3};\n"
        : "+f"(d[0]), "+f"(d[1]), "+f"(d[2]), "+f"(d[3])
        : "r"(a0), "r"(a1), "r"(a2), "r"(a3), "r"(b0), "r"(b1));
}

// ---------------- predictor / top-k ----------------
__global__ void k_init() {
    int t = blockIdx.x * blockDim.x + threadIdx.x;
    if (t < NBINS) g_hist[t] = 0;
    if (t < 4) g_cnt[t] = 0;
}
__global__ void k_pred1(const float* __restrict__ x, const float* __restrict__ W1) {
    const float* xl = x + (size_t)(SEQ - 1) * HIDDEN;
    int warp = (blockIdx.x * blockDim.x + threadIdx.x) >> 5;
    int lane = threadIdx.x & 31;
    if (warp >= PREDH) return;
    const float* w = W1 + (size_t)warp * HIDDEN;
    double s = 0.0;
    for (int k = lane; k < HIDDEN; k += 32) s += (double)w[k] * (double)xl[k];
    for (int o = 16; o; o >>= 1) s += __shfl_down_sync(0xffffffffu, s, o);
    if (lane == 0) g_p[warp] = (float)s;
}
__global__ void k_pred2(const float* __restrict__ W2) {
    int warp = (blockIdx.x * blockDim.x + threadIdx.x) >> 5;
    int lane = threadIdx.x & 31;
    if (warp >= INTER) return;
    const float* w = W2 + (size_t)warp * PREDH;
    double s = 0.0;
    for (int k = lane; k < PREDH; k += 32) s += (double)w[k] * (double)g_p[k];
    for (int o = 16; o; o >>= 1) s += __shfl_down_sync(0xffffffffu, s, o);
    if (lane == 0) {
        float v = (float)s;
        unsigned u = __float_as_uint(v);
        u = (u & 0x80000000u) ? ~u : (u | 0x80000000u);
        g_key[warp] = u;
        atomicAdd(&g_hist[u >> 20], 1);
    }
}
__global__ void k_thresh() {
    __shared__ int s4[1024];
    __shared__ int gsum[32];
    __shared__ int gabove[32];
    int t = threadIdx.x;
    s4[t] = g_hist[4*t] + g_hist[4*t+1] + g_hist[4*t+2] + g_hist[4*t+3];
    __syncthreads();
    if (t < 32) {
        int s = 0;
        for (int j = 0; j < 32; ++j) s += s4[t * 32 + j];
        gsum[t] = s;
    }
    __syncthreads();
    if (t == 0) {
        int acc = 0;
        for (int g = 31; g >= 0; --g) { gabove[g] = acc; acc += gsum[g]; }
        int g = 31;
        while (gabove[g] + gsum[g] < HC) --g;
        acc = gabove[g];
        for (int c = 31; c >= 0; --c) {
            int cell = g * 32 + c;
            int sc = s4[cell];
            if (acc + sc >= HC) {
                for (int bb = 3; bb >= 0; --bb) {
                    int h = g_hist[cell * 4 + bb];
                    if (acc + h >= HC) { g_sel[0] = cell * 4 + bb; g_sel[1] = acc; return; }
                    acc += h;
                }
            }
            acc += sc;
        }
    }
}
__global__ void k_collect() {
    int i = blockIdx.x * blockDim.x + threadIdx.x;
    if (i >= INTER) return;
    unsigned key = g_key[i];
    int bin = g_sel[0];
    int b = (int)(key >> 20);
    if (b > bin) {
        int p = atomicAdd(&g_cnt[0], 1);
        g_idx[p] = i;
    } else if (b == bin) {
        int p = atomicAdd(&g_cnt[1], 1);
        g_cand_idx[p] = i;
        g_cand_key[p] = key;
    }
}
__global__ void k_rank() {
    __shared__ unsigned sk[4096];
    __shared__ int      si[4096];
    int m = g_cnt[1];
    int above = g_sel[1];
    int need = HC - above;
    bool use_s = (m <= 4096);
    if (use_s)
        for (int i = threadIdx.x; i < m; i += blockDim.x) { sk[i]=g_cand_key[i]; si[i]=g_cand_idx[i]; }
    __syncthreads();
    for (int j = threadIdx.x; j < m; j += blockDim.x) {
        unsigned kj = use_s ? sk[j] : g_cand_key[j];
        int ij      = use_s ? si[j] : g_cand_idx[j];
        int r = 0;
        for (int l = 0; l < m; ++l) {
            unsigned kl = use_s ? sk[l] : g_cand_key[l];
            int il      = use_s ? si[l] : g_cand_idx[l];
            r += (int)((kl > kj) || (kl == kj && il < ij));
        }
        if (r < need) g_idx[above + r] = ij;
    }
}

// ---------------- staging: tf32 rounding + 16-block k-transpose ----------------
// P(k) = 16*(k/16) + 4*(k%4) + (k/4)%4  -> fragment float4 loads in the GEMM
__device__ __forceinline__ void transpose_round_store(const float4* in, float* dst) {
    float4 i0 = in[0], i1 = in[1], i2 = in[2], i3 = in[3];
    ((float4*)dst)[0] = make_float4(tfr(i0.x), tfr(i1.x), tfr(i2.x), tfr(i3.x));
    ((float4*)dst)[1] = make_float4(tfr(i0.y), tfr(i1.y), tfr(i2.y), tfr(i3.y));
    ((float4*)dst)[2] = make_float4(tfr(i0.z), tfr(i1.z), tfr(i2.z), tfr(i3.z));
    ((float4*)dst)[3] = make_float4(tfr(i0.w), tfr(i1.w), tfr(i2.w), tfr(i3.w));
}

__global__ void k_round_x(const float* __restrict__ x) {
    int nb = SEQ * HIDDEN / 16;
    for (int b = blockIdx.x * blockDim.x + threadIdx.x; b < nb; b += gridDim.x * blockDim.x)
        transpose_round_store((const float4*)(x + (size_t)b * 16), g_xr + (size_t)b * 16);
}
// row 2k = Wg[idx_k], 2k+1 = Wu[idx_k]; zero pad
__global__ void k_gatherB(const float* __restrict__ Wg, const float* __restrict__ Wu) {
    int r = blockIdx.x;
    int k = r >> 1;
    float* dst = g_b1 + (size_t)r * HIDDEN;
    if (k < HC) {
        const float* src = ((r & 1) ? Wu : Wg) + (size_t)__ldg(&g_idx[k]) * HIDDEN;
        int b = threadIdx.x;  // 256 threads, 256 blocks of 16
        transpose_round_store((const float4*)(src + b * 16), dst + b * 16);
    } else {
        float4* d4 = (float4*)dst;
        for (int j = threadIdx.x; j < HIDDEN / 4; j += 256) d4[j] = make_float4(0,0,0,0);
    }
}
__global__ void k_gatherWd(const float* __restrict__ Wd) {
    int h = blockIdx.x;
    int t = threadIdx.x;            // 64 threads; 48 blocks of 16 in KPAD
    if (t >= KPAD / 16) return;
    const float* row = Wd + (size_t)h * INTER;
    float v[16];
#pragma unroll
    for (int j = 0; j < 16; ++j) {
        int k = t * 16 + j;
        v[j] = (k < HC) ? tfr(__ldg(row + __ldg(&g_idx[k]))) : 0.f;
    }
    float* dst = g_wd + (size_t)h * KPAD + t * 16;
#pragma unroll
    for (int c = 0; c < 4; ++c)
        ((float4*)dst)[c] = make_float4(v[c], v[4+c], v[8+c], v[12+c]);
}

// ---------------- tf32 mma GEMM, permuted-k layout ----------------
// C[M,N] = A[M,K] @ B[N,K]^T.  BM=BN=128, BK=16, 64B smem rows, float4 frags.
// epi=1: B rows interleaved gate/up -> t = tfr(silu(g)*u), permuted-k packed store.
__global__ void __launch_bounds__(256, 2) k_gemm2(
    const float* __restrict__ A, const float* __restrict__ B,
    float* __restrict__ C, int K, int lda, int ldb, int ldc, int epi)
{
    __shared__ float As[2][128 * 16];
    __shared__ float Bs[2][128 * 16];

    int tid = threadIdx.x;
    int lane = tid & 31;
    int warp = tid >> 5;
    int wm = warp >> 2;   // 0..1
    int wn = warp & 3;    // 0..3
    int bm = blockIdx.y * 128;
    int bn = blockIdx.x * 128;

    // cp.async: thread t -> row t>>1, floats (t&1)*8 .. +7 (two 16B chunks)
    int lrow = tid >> 1;
    int lcol = (tid & 1) * 8;
    const float* asrc = A + (size_t)(bm + lrow) * lda + lcol;
    const float* bsrc = B + (size_t)(bn + lrow) * ldb + lcol;
    unsigned sa[2], sb[2];
#pragma unroll
    for (int b = 0; b < 2; ++b) {
        sa[b] = smem_u32(&As[b][lrow * 16 + lcol]);
        sb[b] = smem_u32(&Bs[b][lrow * 16 + lcol]);
    }

    float acc[4][4][4];
#pragma unroll
    for (int i = 0; i < 4; i++)
#pragma unroll
        for (int j = 0; j < 4; j++)
#pragma unroll
            for (int q = 0; q < 4; q++) acc[i][j][q] = 0.f;

    int NT = K / 16;
    auto load = [&](int kt, int buf) {
        int k0 = kt * 16;
        cp16(sa[buf],      asrc + k0);
        cp16(sa[buf] + 16, asrc + k0 + 4);
        cp16(sb[buf],      bsrc + k0);
        cp16(sb[buf] + 16, bsrc + k0 + 4);
        asm volatile("cp.async.commit_group;" ::: "memory");
    };

    load(0, 0);
    int r4 = lane >> 2, c4 = lane & 3;

    for (int kt = 0; kt < NT; ++kt) {
        int buf = kt & 1;
        if (kt + 1 < NT) {
            load(kt + 1, buf ^ 1);
            asm volatile("cp.async.wait_group 1;" ::: "memory");
        } else {
            asm volatile("cp.async.wait_group 0;" ::: "memory");
        }
        __syncthreads();

        const float* as = As[buf];
        const float* bs = Bs[buf];

        float4 vb[4];
#pragma unroll
        for (int ni = 0; ni < 4; ++ni)
            vb[ni] = *(const float4*)&bs[(wn * 32 + ni * 8 + r4) * 16 + c4 * 4];

#pragma unroll
        for (int mi = 0; mi < 4; ++mi) {
            int rbase = wm * 64 + mi * 16 + r4;
            float4 va0 = *(const float4*)&as[rbase * 16 + c4 * 4];
            float4 va1 = *(const float4*)&as[(rbase + 8) * 16 + c4 * 4];
#pragma unroll
            for (int ni = 0; ni < 4; ++ni) {
                mma8(acc[mi][ni],
                     __float_as_uint(va0.x), __float_as_uint(va1.x),
                     __float_as_uint(va0.y), __float_as_uint(va1.y),
                     __float_as_uint(vb[ni].x), __float_as_uint(vb[ni].y));
                mma8(acc[mi][ni],
                     __float_as_uint(va0.z), __float_as_uint(va1.z),
                     __float_as_uint(va0.w), __float_as_uint(va1.w),
                     __float_as_uint(vb[ni].z), __float_as_uint(vb[ni].w));
            }
        }
        __syncthreads();
    }

    if (epi == 1) {
        // fused gate/up epilogue: even col = gate, odd = up.
        // t column = bn/2 + wn*16 + ni*4 + c ; permuted offset = 4c + ni -> float4 over ni.
        int b0 = (bn >> 1) + wn * 16;
#pragma unroll
        for (int mi = 0; mi < 4; ++mi) {
            int r0 = bm + wm * 64 + mi * 16 + r4;
            float o0[4], o1[4];
#pragma unroll
            for (int ni = 0; ni < 4; ++ni) {
                float g0 = acc[mi][ni][0], u0 = acc[mi][ni][1];
                float g1 = acc[mi][ni][2], u1 = acc[mi][ni][3];
                o0[ni] = tfr(u0 * g0 / (1.f + __expf(-g0)));
                o1[ni] = tfr(u1 * g1 / (1.f + __expf(-g1)));
            }
            *(float4*)&C[(size_t)r0 * ldc + b0 + c4 * 4] =
                make_float4(o0[0], o0[1], o0[2], o0[3]);
            *(float4*)&C[(size_t)(r0 + 8) * ldc + b0 + c4 * 4] =
                make_float4(o1[0], o1[1], o1[2], o1[3]);
        }
    } else {
#pragma unroll
        for (int mi = 0; mi < 4; ++mi) {
            int r0 = bm + wm * 64 + mi * 16 + r4;
#pragma unroll
            for (int ni = 0; ni < 4; ++ni) {
                int cc = bn + wn * 32 + ni * 8 + c4 * 2;
                *(float2*)&C[(size_t)r0 * ldc + cc] =
                    make_float2(acc[mi][ni][0], acc[mi][ni][1]);
                *(float2*)&C[(size_t)(r0 + 8) * ldc + cc] =
                    make_float2(acc[mi][ni][2], acc[mi][ni][3]);
            }
        }
    }
}

// ---------------- launch ----------------
extern "C" void kernel_launch(void* const* d_in, const int* in_sizes, int n_in,
                              void* d_out, int out_size) {
    (void)in_sizes; (void)n_in; (void)out_size;
    const float* x  = (const float*)d_in[0];
    const float* Wg = (const float*)d_in[1];
    const float* Wu = (const float*)d_in[2];
    const float* Wd = (const float*)d_in[3];
    const float* W1 = (const float*)d_in[4];
    const float* W2 = (const float*)d_in[5];
    float* out = (float*)d_out;

    float *pxr = nullptr, *pb1 = nullptr, *pwd = nullptr, *pt = nullptr;
    cudaGetSymbolAddress((void**)&pxr, g_xr);
    cudaGetSymbolAddress((void**)&pb1, g_b1);
    cudaGetSymbolAddress((void**)&pwd, g_wd);
    cudaGetSymbolAddress((void**)&pt,  g_t);

    k_init<<<16, 256>>>();
    k_pred1<<<(PREDH * 32) / 256, 256>>>(x, W1);
    k_pred2<<<(INTER * 32) / 256, 256>>>(W2);
    k_thresh<<<1, 1024>>>();
    k_collect<<<(INTER + 255) / 256, 256>>>();
    k_rank<<<1, 512>>>();
    k_round_x<<<2048, 256>>>(x);
    k_gatherB<<<NPAD, 256>>>(Wg, Wu);
    k_gatherWd<<<HIDDEN, 64>>>(Wd);

    // fused gate/up: [4096 x 1536] -> t[4096 x 768 (permuted)]
    dim3 g1(NPAD / 128, SEQ / 128);
    k_gemm2<<<g1, 256>>>(pxr, pb1, pt, HIDDEN, HIDDEN, HIDDEN, KPAD, 1);
    // down: out[4096 x 4096] = t @ wd^T
    dim3 g2(HIDDEN / 128, SEQ / 128);
    k_gemm2<<<g2, 256>>>(pt, pwd, out, KPAD, KPAD, KPAD, HIDDEN, 0);
}